// round 7
// baseline (speedup 1.0000x reference)
#include <cuda_runtime.h>

// ============================================================================
// GCNMultiRegressor — layer-2 collapsed; fp32 xs; column-split aggregation
// (3 warps per node, 150k warp-tasks); 3-stream fork under graph capture:
//   s1: gemm1 (xs = feat@W1)                  [input-only]
//   s0: zero -> build -> c (inline norm_in)
//   s2: norms (tables for agg)                [after build]
//   join -> agg3 (fused relu + layer-2 collapse) -> final
// ============================================================================

#define NMAX 50048
#define HD 96
#define CAP 64

__device__ int   g_cnt_in[NMAX];
__device__ int   g_cnt_out[NMAX];
__device__ int   g_bucket[(size_t)NMAX * CAP];
__device__ float g_norm_in[NMAX];
__device__ float g_norm_out[NMAX];
__device__ float g_c[NMAX];
__device__ float g_xs[(size_t)NMAX * HD];
__device__ float g_colvec[HD];

// --- capture-fork resources (created once at load; no device mem alloc) ----
static cudaStream_t g_s1, g_s2;
static cudaEvent_t  g_e0, g_e1, g_eb, g_en;
namespace {
struct StreamInit {
    StreamInit() {
        cudaStreamCreateWithFlags(&g_s1, cudaStreamNonBlocking);
        cudaStreamCreateWithFlags(&g_s2, cudaStreamNonBlocking);
        cudaEventCreateWithFlags(&g_e0, cudaEventDisableTiming);
        cudaEventCreateWithFlags(&g_e1, cudaEventDisableTiming);
        cudaEventCreateWithFlags(&g_eb, cudaEventDisableTiming);
        cudaEventCreateWithFlags(&g_en, cudaEventDisableTiming);
    }
};
StreamInit g_stream_init;
}

// ---------------------------------------------------------------------------
__global__ void k_zero(int n) {
    int i = blockIdx.x * blockDim.x + threadIdx.x;
    if (i < n) { g_cnt_in[i] = 0; g_cnt_out[i] = 0; g_c[i] = 0.0f; }
    if (i < HD) g_colvec[i] = 0.0f;
}

__global__ void k_build(const int* __restrict__ src, const int* __restrict__ dst, int e) {
    int i = blockIdx.x * blockDim.x + threadIdx.x;
    if (i < e) {
        int d = dst[i];
        int p = atomicAdd(&g_cnt_in[d], 1);
        if (p < CAP) g_bucket[(size_t)d * CAP + p] = src[i];
        atomicAdd(&g_cnt_out[src[i]], 1);
    }
}

__global__ void k_norms(int n) {
    int i = blockIdx.x * blockDim.x + threadIdx.x;
    if (i < n) {
        int di = g_cnt_in[i], dq = g_cnt_out[i];
        g_norm_in[i]  = rsqrtf((float)(di > 1 ? di : 1));
        g_norm_out[i] = rsqrtf((float)(dq > 1 ? dq : 1));
    }
}

// c[src] += norm_in[dst], norm_in computed inline (no table dependency).
__global__ void k_c(const int* __restrict__ src, const int* __restrict__ dst, int e) {
    int i = blockIdx.x * blockDim.x + threadIdx.x;
    if (i < e) {
        int cin = g_cnt_in[dst[i]];
        float ni = rsqrtf((float)(cin > 1 ? cin : 1));
        atomicAdd(&g_c[src[i]], ni);
    }
}

// xs = feat @ W1 (raw fp32). R2-proven tile.
__global__ void k_gemm1(const float* __restrict__ X, const float* __restrict__ W, int n) {
    __shared__ float sW[HD * HD];   // 36 KB
    __shared__ float sX[32 * HD];   // 12 KB
    int tid = threadIdx.x;
    int n0  = blockIdx.x * 32;
    for (int i = tid; i < HD * HD; i += 256) sW[i] = W[i];
    for (int i = tid; i < 32 * HD; i += 256) {
        int nn = n0 + (i / HD);
        sX[i] = (nn < n) ? X[(size_t)nn * HD + (i % HD)] : 0.f;
    }
    __syncthreads();
    int tx = tid & 31, ty = tid >> 5;
    float acc[4][3] = {};
#pragma unroll 8
    for (int k = 0; k < HD; k++) {
        float w0 = sW[k * HD + tx];
        float w1 = sW[k * HD + tx + 32];
        float w2 = sW[k * HD + tx + 64];
#pragma unroll
        for (int j = 0; j < 4; j++) {
            float xv = sX[(ty + 8 * j) * HD + k];
            acc[j][0] = fmaf(xv, w0, acc[j][0]);
            acc[j][1] = fmaf(xv, w1, acc[j][1]);
            acc[j][2] = fmaf(xv, w2, acc[j][2]);
        }
    }
#pragma unroll
    for (int j = 0; j < 4; j++) {
        int nn = n0 + ty + 8 * j;
        if (nn < n) {
            float* o = g_xs + (size_t)nn * HD;
            o[tx]      = acc[j][0];
            o[tx + 32] = acc[j][1];
            o[tx + 64] = acc[j][2];
        }
    }
}

// Column-split aggregation: warp-task t -> (node = t/3, colgroup = t%3).
// Each warp: 1 aligned LDG.32 per neighbor (its 128B column segment),
// per-edge norm_out scale, fused relu + layer-2 collapse, register colvec
// accumulation (colgroup is loop-invariant: stride 9480 % 3 == 0).
__global__ void k_agg3(const float* __restrict__ b1v, int n) {
    __shared__ float scol[HD];
    int tid = threadIdx.x, lane = tid & 31, wid = tid >> 5;
    if (tid < HD) scol[tid] = 0.0f;
    __syncthreads();

    int wpb   = blockDim.x >> 5;
    int gw    = blockIdx.x * wpb + wid;
    int totw  = gridDim.x * wpb;          // 1185*8 = 9480, divisible by 3
    int ntask = 3 * n;

    int cg  = gw % 3;                     // loop-invariant column group
    int col = cg * 32 + lane;
    float bb  = b1v[col];
    float acc = 0.0f;

    for (int t = gw; t < ntask; t += totw) {
        int node = t / 3;
        int d = g_cnt_in[node];
        if (d > CAP) d = CAP;
        const int* __restrict__ lst = g_bucket + (size_t)node * CAP;
        float a = 0.0f;
        int j = 0;
        for (; j + 4 <= d; j += 4) {
            int4 q = *(const int4*)(lst + j);
            float f0 = g_norm_out[q.x];
            float f1 = g_norm_out[q.y];
            float f2 = g_norm_out[q.z];
            float f3 = g_norm_out[q.w];
            float v0 = g_xs[(size_t)q.x * HD + col];
            float v1 = g_xs[(size_t)q.y * HD + col];
            float v2 = g_xs[(size_t)q.z * HD + col];
            float v3 = g_xs[(size_t)q.w * HD + col];
            a = fmaf(f0, v0, a);
            a = fmaf(f1, v1, a);
            a = fmaf(f2, v2, a);
            a = fmaf(f3, v3, a);
        }
        for (; j < d; j++) {
            int s = lst[j];
            a = fmaf(g_norm_out[s], g_xs[(size_t)s * HD + col], a);
        }
        float ni = g_norm_in[node];
        float w  = g_norm_out[node] * g_c[node];
        acc = fmaf(w, fmaxf(fmaf(ni, a, bb), 0.f), acc);
    }
    atomicAdd(&scol[col], acc);
    __syncthreads();
    if (tid < HD) atomicAdd(&g_colvec[tid], scol[tid]);
}

// hg = colvec/N @ W2 + b2 ; out = hg @ Wr^T + br
__global__ void k_final(const float* __restrict__ W2, const float* __restrict__ b2,
                        const float* __restrict__ Wr, const float* __restrict__ br,
                        float* __restrict__ out, int n) {
    __shared__ float hg[HD];
    int t = threadIdx.x;            // blockDim = 96
    float inv = 1.0f / (float)n;
    float a = 0.f;
#pragma unroll 8
    for (int k = 0; k < HD; k++) a = fmaf(g_colvec[k] * inv, W2[k * HD + t], a);
    hg[t] = a + b2[t];
    __syncthreads();
    if (t < 8) {
        float o = 0.f;
#pragma unroll 8
        for (int k = 0; k < HD; k++) o = fmaf(hg[k], Wr[t * HD + k], o);
        out[t] = o + br[t];
    }
}

// ---------------------------------------------------------------------------
extern "C" void kernel_launch(void* const* d_in, const int* in_sizes, int n_in,
                              void* d_out, int out_size) {
    const float* feat = (const float*)d_in[0];
    const int*   src  = (const int*)d_in[1];
    const int*   dst  = (const int*)d_in[2];
    const float* W1   = (const float*)d_in[3];
    const float* b1   = (const float*)d_in[4];
    const float* W2   = (const float*)d_in[5];
    const float* b2   = (const float*)d_in[6];
    const float* Wr   = (const float*)d_in[7];
    const float* br   = (const float*)d_in[8];
    float* out = (float*)d_out;

    int n = in_sizes[0] / HD;   // 50000
    int e = in_sizes[1];        // 800000

    // Fork s1: GEMM (input-only).
    cudaEventRecord(g_e0, 0);
    cudaStreamWaitEvent(g_s1, g_e0, 0);
    k_gemm1<<<(n + 31) / 32, 256, 0, g_s1>>>(feat, W1, n);
    cudaEventRecord(g_e1, g_s1);

    // s0: edge/build chain.
    k_zero <<<(n + 255) / 256, 256>>>(n);
    k_build<<<(e + 255) / 256, 256>>>(src, dst, e);
    cudaEventRecord(g_eb, 0);

    // Fork s2: norm tables (after build), overlapped with k_c.
    cudaStreamWaitEvent(g_s2, g_eb, 0);
    k_norms<<<(n + 255) / 256, 256, 0, g_s2>>>(n);
    cudaEventRecord(g_en, g_s2);

    k_c<<<(e + 255) / 256, 256>>>(src, dst, e);   // inline norm_in

    // Join, then aggregate + readout.
    cudaStreamWaitEvent(0, g_e1, 0);
    cudaStreamWaitEvent(0, g_en, 0);
    k_agg3 <<<1185, 256>>>(b1, n);
    k_final<<<1, HD>>>(W2, b2, Wr, br, out, n);
}

// round 8
// speedup vs baseline: 1.1399x; 1.1399x over previous
#include <cuda_runtime.h>

// ============================================================================
// GCNMultiRegressor — layer-2 collapsed; restructured DAG:
//   s1: gemm1 (xs = feat@W1)              [input-only]
//   s2: zero_out -> degout (cnt_out)      [input-only: reads src]
//   s0: zero -> build (cnt_in+bucket) -> c (inline norm_in)
//   join -> agg (warp-per-node, inline norms, fused relu + collapse + readout)
// norms tables eliminated (inline rsqrtf); final kernel fused via last-block.
// ============================================================================

#define NMAX 50048
#define HD 96
#define CAP 64

__device__ int   g_cnt_in[NMAX];
__device__ int   g_cnt_out[NMAX];
__device__ int   g_bucket[(size_t)NMAX * CAP];
__device__ float g_c[NMAX];
__device__ float g_xs[(size_t)NMAX * HD];
__device__ float g_colvec[HD];
__device__ int   g_done;

// --- capture-fork resources (created once at load; no device mem alloc) ----
static cudaStream_t g_s1, g_s2;
static cudaEvent_t  g_e0, g_e1, g_e2;
namespace {
struct StreamInit {
    StreamInit() {
        cudaStreamCreateWithFlags(&g_s1, cudaStreamNonBlocking);
        cudaStreamCreateWithFlags(&g_s2, cudaStreamNonBlocking);
        cudaEventCreateWithFlags(&g_e0, cudaEventDisableTiming);
        cudaEventCreateWithFlags(&g_e1, cudaEventDisableTiming);
        cudaEventCreateWithFlags(&g_e2, cudaEventDisableTiming);
    }
};
StreamInit g_stream_init;
}

// ---------------------------------------------------------------------------
__global__ void k_zero(int n) {
    int i = blockIdx.x * blockDim.x + threadIdx.x;
    if (i < n) { g_cnt_in[i] = 0; g_c[i] = 0.0f; }
    if (i < HD) g_colvec[i] = 0.0f;
    if (i == 0) g_done = 0;
}

__global__ void k_zero_out(int n) {
    int i = blockIdx.x * blockDim.x + threadIdx.x;
    if (i < n) g_cnt_out[i] = 0;
}

// Out-degree only — input-only dependency (reads src), runs on s2.
__global__ void k_degout(const int* __restrict__ src, int e) {
    int i0 = (blockIdx.x * blockDim.x + threadIdx.x) * 2;
    if (i0 + 1 < e) {
        int2 s = *(const int2*)(src + i0);
        atomicAdd(&g_cnt_out[s.x], 1);
        atomicAdd(&g_cnt_out[s.y], 1);
    } else if (i0 < e) {
        atomicAdd(&g_cnt_out[src[i0]], 1);
    }
}

// In-degree count + bucket placement (one returning atomic + store per edge).
__global__ void k_build(const int* __restrict__ src, const int* __restrict__ dst, int e) {
    int i0 = (blockIdx.x * blockDim.x + threadIdx.x) * 2;
    if (i0 + 1 < e) {
        int2 s = *(const int2*)(src + i0);
        int2 d = *(const int2*)(dst + i0);
        int p0 = atomicAdd(&g_cnt_in[d.x], 1);
        int p1 = atomicAdd(&g_cnt_in[d.y], 1);
        if (p0 < CAP) g_bucket[(size_t)d.x * CAP + p0] = s.x;
        if (p1 < CAP) g_bucket[(size_t)d.y * CAP + p1] = s.y;
    } else if (i0 < e) {
        int d = dst[i0];
        int p = atomicAdd(&g_cnt_in[d], 1);
        if (p < CAP) g_bucket[(size_t)d * CAP + p] = src[i0];
    }
}

// c[src] += norm_in[dst], norm_in inlined from cnt_in.
__global__ void k_c(const int* __restrict__ src, const int* __restrict__ dst, int e) {
    int i0 = (blockIdx.x * blockDim.x + threadIdx.x) * 2;
    if (i0 + 1 < e) {
        int2 s = *(const int2*)(src + i0);
        int2 d = *(const int2*)(dst + i0);
        int c0 = g_cnt_in[d.x];
        int c1 = g_cnt_in[d.y];
        float n0 = rsqrtf((float)(c0 > 1 ? c0 : 1));
        float n1 = rsqrtf((float)(c1 > 1 ? c1 : 1));
        atomicAdd(&g_c[s.x], n0);
        atomicAdd(&g_c[s.y], n1);
    } else if (i0 < e) {
        int cin = g_cnt_in[dst[i0]];
        float ni = rsqrtf((float)(cin > 1 ? cin : 1));
        atomicAdd(&g_c[src[i0]], ni);
    }
}

// xs = feat @ W1 (raw fp32). R2-proven tile.
__global__ void k_gemm1(const float* __restrict__ X, const float* __restrict__ W, int n) {
    __shared__ float sW[HD * HD];   // 36 KB
    __shared__ float sX[32 * HD];   // 12 KB
    int tid = threadIdx.x;
    int n0  = blockIdx.x * 32;
    for (int i = tid; i < HD * HD; i += 256) sW[i] = W[i];
    for (int i = tid; i < 32 * HD; i += 256) {
        int nn = n0 + (i / HD);
        sX[i] = (nn < n) ? X[(size_t)nn * HD + (i % HD)] : 0.f;
    }
    __syncthreads();
    int tx = tid & 31, ty = tid >> 5;
    float acc[4][3] = {};
#pragma unroll 8
    for (int k = 0; k < HD; k++) {
        float w0 = sW[k * HD + tx];
        float w1 = sW[k * HD + tx + 32];
        float w2 = sW[k * HD + tx + 64];
#pragma unroll
        for (int j = 0; j < 4; j++) {
            float xv = sX[(ty + 8 * j) * HD + k];
            acc[j][0] = fmaf(xv, w0, acc[j][0]);
            acc[j][1] = fmaf(xv, w1, acc[j][1]);
            acc[j][2] = fmaf(xv, w2, acc[j][2]);
        }
    }
#pragma unroll
    for (int j = 0; j < 4; j++) {
        int nn = n0 + ty + 8 * j;
        if (nn < n) {
            float* o = g_xs + (size_t)nn * HD;
            o[tx]      = acc[j][0];
            o[tx + 32] = acc[j][1];
            o[tx + 64] = acc[j][2];
        }
    }
}

__device__ __forceinline__ float nout(int s) {
    int q = g_cnt_out[s];
    return rsqrtf((float)(q > 1 ? q : 1));
}

// Warp-per-node aggregation (R5-proven core), inline norms, fused relu +
// layer-2 collapse, and LAST-BLOCK readout (no separate final kernel).
__global__ void k_agg(const float* __restrict__ b1v,
                      const float* __restrict__ W2, const float* __restrict__ b2,
                      const float* __restrict__ Wr, const float* __restrict__ br,
                      float* __restrict__ out, int n) {
    __shared__ float scol[HD];
    int tid = threadIdx.x, lane = tid & 31, wid = tid >> 5;
    if (tid < HD) scol[tid] = 0.0f;
    __syncthreads();

    float bb0 = b1v[lane], bb1 = b1v[lane + 32], bb2 = b1v[lane + 64];
    float c0 = 0.f, c1 = 0.f, c2 = 0.f;
    int wpb  = blockDim.x >> 5;
    int totw = gridDim.x * wpb;

    for (int node = blockIdx.x * wpb + wid; node < n; node += totw) {
        int d = g_cnt_in[node];
        if (d > CAP) d = CAP;
        const int* __restrict__ lst = g_bucket + (size_t)node * CAP;
        float a0 = 0.f, a1 = 0.f, a2 = 0.f;
        int j = 0;
        for (; j + 4 <= d; j += 4) {
            int4 q = *(const int4*)(lst + j);
            float f0 = nout(q.x), f1 = nout(q.y), f2 = nout(q.z), f3 = nout(q.w);
            const float* __restrict__ r0 = g_xs + (size_t)q.x * HD;
            const float* __restrict__ r1 = g_xs + (size_t)q.y * HD;
            const float* __restrict__ r2 = g_xs + (size_t)q.z * HD;
            const float* __restrict__ r3 = g_xs + (size_t)q.w * HD;
            a0 = fmaf(f0, r0[lane], a0); a1 = fmaf(f0, r0[lane+32], a1); a2 = fmaf(f0, r0[lane+64], a2);
            a0 = fmaf(f1, r1[lane], a0); a1 = fmaf(f1, r1[lane+32], a1); a2 = fmaf(f1, r1[lane+64], a2);
            a0 = fmaf(f2, r2[lane], a0); a1 = fmaf(f2, r2[lane+32], a1); a2 = fmaf(f2, r2[lane+64], a2);
            a0 = fmaf(f3, r3[lane], a0); a1 = fmaf(f3, r3[lane+32], a1); a2 = fmaf(f3, r3[lane+64], a2);
        }
        for (; j < d; j++) {
            int s = lst[j];
            float f = nout(s);
            const float* __restrict__ r = g_xs + (size_t)s * HD;
            a0 = fmaf(f, r[lane], a0);
            a1 = fmaf(f, r[lane + 32], a1);
            a2 = fmaf(f, r[lane + 64], a2);
        }
        int   di = g_cnt_in[node];
        float ni = rsqrtf((float)(di > 1 ? di : 1));
        float w  = nout(node) * g_c[node];
        c0 = fmaf(w, fmaxf(fmaf(ni, a0, bb0), 0.f), c0);
        c1 = fmaf(w, fmaxf(fmaf(ni, a1, bb1), 0.f), c1);
        c2 = fmaf(w, fmaxf(fmaf(ni, a2, bb2), 0.f), c2);
    }
    atomicAdd(&scol[lane],      c0);
    atomicAdd(&scol[lane + 32], c1);
    atomicAdd(&scol[lane + 64], c2);
    __syncthreads();
    if (tid < HD) atomicAdd(&g_colvec[tid], scol[tid]);

    // ---- last-block fused readout ----
    __threadfence();
    __shared__ int slast;
    if (tid == 0) slast = (atomicAdd(&g_done, 1) == (int)gridDim.x - 1);
    __syncthreads();
    if (slast) {
        __threadfence();                      // acquire side
        __shared__ float hg[HD];
        if (tid < HD) {
            volatile float* cv = g_colvec;
            float inv = 1.0f / (float)n;
            float a = 0.f;
#pragma unroll 8
            for (int k = 0; k < HD; k++) a = fmaf(cv[k] * inv, W2[k * HD + tid], a);
            hg[tid] = a + b2[tid];
        }
        __syncthreads();
        if (tid < 8) {
            float o = 0.f;
#pragma unroll 8
            for (int k = 0; k < HD; k++) o = fmaf(hg[k], Wr[tid * HD + k], o);
            out[tid] = o + br[tid];
        }
    }
}

// ---------------------------------------------------------------------------
extern "C" void kernel_launch(void* const* d_in, const int* in_sizes, int n_in,
                              void* d_out, int out_size) {
    const float* feat = (const float*)d_in[0];
    const int*   src  = (const int*)d_in[1];
    const int*   dst  = (const int*)d_in[2];
    const float* W1   = (const float*)d_in[3];
    const float* b1   = (const float*)d_in[4];
    const float* W2   = (const float*)d_in[5];
    const float* b2   = (const float*)d_in[6];
    const float* Wr   = (const float*)d_in[7];
    const float* br   = (const float*)d_in[8];
    float* out = (float*)d_out;

    int n = in_sizes[0] / HD;   // 50000
    int e = in_sizes[1];        // 800000
    int eb2 = (e / 2 + 255) / 256;   // ILP-2 edge blocks

    cudaEventRecord(g_e0, 0);

    // s1: GEMM (input-only)
    cudaStreamWaitEvent(g_s1, g_e0, 0);
    k_gemm1<<<(n + 31) / 32, 256, 0, g_s1>>>(feat, W1, n);
    cudaEventRecord(g_e1, g_s1);

    // s2: out-degree leg (input-only)
    cudaStreamWaitEvent(g_s2, g_e0, 0);
    k_zero_out<<<(n + 255) / 256, 256, 0, g_s2>>>(n);
    k_degout  <<<eb2, 256, 0, g_s2>>>(src, e);
    cudaEventRecord(g_e2, g_s2);

    // s0: in-degree/bucket/c chain
    k_zero <<<(n + 255) / 256, 256>>>(n);
    k_build<<<eb2, 256>>>(src, dst, e);
    k_c    <<<eb2, 256>>>(src, dst, e);

    // join, aggregate (+fused readout)
    cudaStreamWaitEvent(0, g_e1, 0);
    cudaStreamWaitEvent(0, g_e2, 0);
    k_agg<<<592, 256>>>(b1, W2, b2, Wr, br, out, n);
}